// round 11
// baseline (speedup 1.0000x reference)
#include <cuda_runtime.h>
#include <cstdint>
#include <math.h>

// Problem dims
#define BB 16
#define NN 64
#define DD 512
#define PP 64
#define QQ 16
#define CELL 1024   // PP*QQ

// Output offsets (flat concat of reference return tuple, fp32)
#define OFF_M     0LL
#define OFF_MP    67108864LL
#define OFF_Q     134217728LL
#define OFF_K     134742016LL
#define OFF_COS   135266304LL
#define OFF_ABN   135266320LL
#define OFF_ABDJ  135274512LL
#define OFF_CT    135798800LL
#define OFF_CS    135864336LL
#define OFF_CDBL  135929872LL
#define OFF_PHAT  135995408LL

// Group barriers (group A = warps 0-7 = 256 thr; group B = warps 8-11 = 128 thr)
#define BARA() asm volatile("bar.sync 1, 256;" ::: "memory")
#define BARB() asm volatile("bar.sync 2, 128;" ::: "memory")

// Scratch (__device__ globals: allocation-free)
__device__ float g_bias_bar[NN * CELL];
__device__ float g_bqp[32 * DD * NN];
__device__ float g_bkp[32 * DD * NN];
__device__ int   g_f_abn;
__device__ int   g_f_biasbar;
__device__ int   g_f_bq;
__device__ int   g_done;

// Shared layout: A region = [0, 5120) floats (bias 4096 + d_ctx 1024).
// B region = [5120, 5120+6384). Total 11504 floats = 46 KB static smem.
__global__ void __launch_bounds__(384) k_fused(
        const float* __restrict__ a, const float* __restrict__ bvec,
        const float* __restrict__ c, const float* __restrict__ dctx,
        const float* __restrict__ alpha, const float* __restrict__ bias,
        const float* __restrict__ wq, const float* __restrict__ wk,
        const float* __restrict__ abd_w, const float* __restrict__ abd_b,
        const float* __restrict__ ctx_w, const float* __restrict__ ctx_b,
        const float* __restrict__ w1, const float* __restrict__ b1,
        const float* __restrict__ w_prob, const float* __restrict__ b_prob,
        float* __restrict__ out) {
    __shared__ float4 pool4[2876];          // 11504 floats = 46016 B
    float* pool = (float*)pool4;
    float* poolB = pool + 5120;
    int bid = blockIdx.x;                   // 0..1023
    int t = threadIdx.x;

    if (t < 256) {
        // ================= GROUP A: BIG store tile (i, j-chunk) =================
        int i  = bid >> 4;
        int j0 = (bid & 15) * 4;
        float* s_bias = pool;               // 4096
        float* s_d    = pool + 4096;        // 1024

        float ap = 1.f + alpha[0];
        float s3 = ap * ap * ap;
        float tb = ap * ap + ap + 1.f;

        {
            const float4* src = (const float4*)(bias + ((size_t)i * NN + j0) * CELL);
            float4* dst = (float4*)s_bias;
#pragma unroll
            for (int it = 0; it < 4; it++) dst[t + 256 * it] = src[t + 256 * it];
        }
        {
            int b = t >> 4, j = (t >> 2) & 3, qv = t & 3;
            ((float4*)s_d)[t] = *(const float4*)(dctx + ((size_t)b * NN + j0 + j) * QQ + qv * 4);
        }
        int p = t >> 2;
        int qv = t & 3;
        float cvs[16];
#pragma unroll
        for (int b = 0; b < BB; b++) cvs[b] = c[((size_t)b * NN + i) * PP + p];
        BARA();

        float4* outbase = (float4*)out;
        const float4* sd4 = (const float4*)s_d;
        const float4* sb4 = (const float4*)s_bias;

        for (int b = 0; b < BB; b++) {
            float cv = cvs[b];
            size_t row = ((size_t)(b * NN + i) * NN + j0) * 256;
#pragma unroll
            for (int j = 0; j < 4; j++) {
                float4 d4 = sd4[(b * 4 + j) * 4 + qv];
                float4 bv = sb4[j * 256 + t];
                float4 mv;
                mv.x = cv * d4.x; mv.y = cv * d4.y; mv.z = cv * d4.z; mv.w = cv * d4.w;
                float4 mp;
                mp.x = s3 * mv.x + tb * bv.x;
                mp.y = s3 * mv.y + tb * bv.y;
                mp.z = s3 * mv.z + tb * bv.z;
                mp.w = s3 * mv.w + tb * bv.w;
                __stcs(&outbase[row + j * 256 + t], mv);
                __stcs(&outbase[(OFF_MP / 4) + row + j * 256 + t], mp);
            }
        }
        return;
    }

    // ===================== GROUP B: tail + chain (128 thr) =====================
    int t2 = t - 256;                       // 0..127

    // ---- Phase 1: producers ----
    if (bid < 16) {
        // ABN: cos_ab + abn for b = bid
        int b = bid;
        float* ra = poolB;                  // 128
        float* rb = poolB + 128;
        float* rab = poolB + 256;
        float* s_cos = poolB + 384;
        float sa = 0.f, sb = 0.f, sab = 0.f;
        for (int d = t2; d < DD; d += 128) {
            float av = a[b * DD + d], bv = bvec[b * DD + d];
            sa += av * av; sb += bv * bv; sab += av * bv;
        }
        ra[t2] = sa; rb[t2] = sb; rab[t2] = sab;
        BARB();
        for (int s = 64; s > 0; s >>= 1) {
            if (t2 < s) { ra[t2] += ra[t2 + s]; rb[t2] += rb[t2 + s]; rab[t2] += rab[t2 + s]; }
            BARB();
        }
        if (t2 == 0) {
            float na = fmaxf(sqrtf(ra[0]), 1e-8f);
            float nb = fmaxf(sqrtf(rb[0]), 1e-8f);
            float cosv = rab[0] / (na * nb);
            s_cos[0] = cosv;
            out[OFF_COS + b] = cosv;
        }
        BARB();
        float cosv = s_cos[0];
        for (int d = t2; d < DD; d += 128) {
            out[OFF_ABN + (long long)b * DD + d] =
                tanhf(a[b * DD + d] * (1.f - cosv)) + tanhf(bvec[b * DD + d] * cosv);
        }
        __threadfence();
        BARB();
        if (t2 == 0) atomicAdd(&g_f_abn, 1);
    } else if (bid < 272) {
        // BIASBAR: chunk (i, c0) of 256 columns
        int id = bid - 16;
        int i = id >> 2;
        int c0 = (id & 3) * 256;
#pragma unroll
        for (int k = 0; k < 2; k++) {
            int cc = c0 + t2 + k * 128;
            float s = 0.f;
            const float* base = bias + (size_t)i * NN * CELL + cc;
#pragma unroll 8
            for (int j = 0; j < NN; j++) s += base[(size_t)j * CELL];
            g_bias_bar[i * CELL + cc] = s * (1.f / NN);
        }
        __threadfence();
        BARB();
        if (t2 == 0) atomicAdd(&g_f_biasbar, 1);
    }

    // ---- Phase 2: TAIL for bn = bid (waits f_abn) ----
    {
        int bn = bid;
        int b = bn >> 6, n = bn & 63;
        float* s_ct   = poolB;              // 64
        float* s_cs   = poolB + 64;         // 64
        float* s_abdj = poolB + 128;        // 512
        float* s_dd   = poolB + 640;        // 16
        float* red    = poolB + 656;        // 128
        float* red2   = poolB + 784;        // 128
        float* s_stat = poolB + 912;        // 2
        float* s_p    = poolB + 914;        // 2

        if (t2 == 0) {
            while (atomicAdd(&g_f_abn, 0) < 16) __nanosleep(32);
        }
        BARB();
        __threadfence();

        if (t2 < QQ) s_dd[t2] = dctx[bn * QQ + t2];
        float v = 0.f;
        if (t2 < 64) { v = 64.f * c[(size_t)bn * 64 + t2]; s_ct[t2] = v; }
        BARB();
        if (t2 < 32) {
            float m = fmaxf(s_ct[t2], s_ct[t2 + 32]);
#pragma unroll
            for (int o = 16; o > 0; o >>= 1) m = fmaxf(m, __shfl_xor_sync(0xffffffffu, m, o));
            if (t2 == 0) s_stat[0] = m;
        }
        BARB();
        float e = 0.f;
        if (t2 < 64) e = expf(v - s_stat[0]);
        red[t2] = (t2 < 64) ? e : 0.f;
        BARB();
        if (t2 < 32) {
            float s = red[t2] + red[t2 + 32];
#pragma unroll
            for (int o = 16; o > 0; o >>= 1) s += __shfl_xor_sync(0xffffffffu, s, o);
            if (t2 == 0) s_stat[1] = s;
        }
        BARB();
        if (t2 < 64) {
            float ct = e / s_stat[1];
            s_ct[t2] = ct;
            out[OFF_CT + (long long)bn * 64 + t2] = ct;
        }
        BARB();

        if (t2 < 64) {
            float acc = b1[n * 64 + t2];
            const float* w1r = w1 + ((size_t)n * 64 + t2) * 64;
#pragma unroll 8
            for (int p = 0; p < 64; p++) acc += s_ct[p] * w1r[p];
            float cs = fmaxf(acc, 0.f);
            s_cs[t2] = cs;
            out[OFF_CS + (long long)bn * 64 + t2] = cs;
        }
        for (int d = t2; d < DD; d += 128) {
            float dp = ctx_b[d];
            const float* cw = ctx_w + d * QQ;
#pragma unroll
            for (int q = 0; q < QQ; q++) dp += s_dd[q] * cw[q];
            float abn = out[OFF_ABN + (long long)b * DD + d];   // precomputed
            float val = tanhf(abd_w[n * DD + d] * abn * dp + abd_b[n * DD + d]);
            s_abdj[d] = val;
            out[OFF_ABDJ + (long long)bn * DD + d] = val;
        }
        BARB();

        float l0 = 0.f, l1 = 0.f;
        const float* wp0 = w_prob + (size_t)(n * 2 + 0) * 576;
        const float* wp1 = w_prob + (size_t)(n * 2 + 1) * 576;
        for (int k = t2; k < 576; k += 128) {
            float cb = (k < 64) ? s_cs[k] : s_abdj[k - 64];
            l0 += cb * wp0[k];
            l1 += cb * wp1[k];
        }
        red[t2] = l0; red2[t2] = l1;
        BARB();
        for (int s = 64; s > 0; s >>= 1) {
            if (t2 < s) { red[t2] += red[t2 + s]; red2[t2] += red2[t2 + s]; }
            BARB();
        }
        if (t2 == 0) {
            float L0 = red[0] + b_prob[n * 2 + 0];
            float L1 = red2[0] + b_prob[n * 2 + 1];
            float m = fmaxf(L0, L1);
            float e0 = expf(L0 - m), e1 = expf(L1 - m);
            float inv = 1.f / (e0 + e1);
            s_p[0] = e0 * inv; s_p[1] = e1 * inv;
            out[OFF_PHAT + (long long)bn * 2 + 0] = s_p[0];
            out[OFF_PHAT + (long long)bn * 2 + 1] = s_p[1];
        }
        BARB();
        if (t2 < 64) {
            float cs = s_cs[t2];
            out[OFF_CDBL + (long long)bn * 64 + t2] = tanhf(s_p[0] * cs) + tanhf(s_p[1] * cs);
        }
        BARB();   // release B smem for phase 3
    }

    // ---- Phase 3: bq (blocks 0-511) or proj (blocks 512-1023) ----
    if (bid < 512) {
        // BQ/BK partials for (dt, cb): 32d x 64n over c-chunk of 32
        int dt = bid >> 5, cb = bid & 31;
        int c0 = cb * 32;
        int tx = t2 & 15, ty = t2 >> 4;     // ty 0..7
        float* sbb = poolB;                 // 64 x 33 = 2112
        float* swq = poolB + 2112;          // 32 x 33 = 1056
        float* swk = poolB + 3168;          // 1056

        if (t2 == 0) {
            while (atomicAdd(&g_f_biasbar, 0) < 256) __nanosleep(64);
        }
        BARB();
        __threadfence();

#pragma unroll
        for (int it = 0; it < 4; it++) {
            int idx = t2 + 128 * it;         // 0..511
            int n = idx >> 3, c4 = idx & 7;
            float4 v = *(const float4*)(g_bias_bar + n * CELL + c0 + c4 * 4);
            sbb[n * 33 + c4 * 4 + 0] = v.x; sbb[n * 33 + c4 * 4 + 1] = v.y;
            sbb[n * 33 + c4 * 4 + 2] = v.z; sbb[n * 33 + c4 * 4 + 3] = v.w;
        }
#pragma unroll
        for (int it = 0; it < 2; it++) {
            int idx = t2 + 128 * it;         // 0..255
            int r = idx >> 3, c4 = idx & 7;
            float4 q = *(const float4*)(wq + (size_t)(dt * 32 + r) * CELL + c0 + c4 * 4);
            float4 k = *(const float4*)(wk + (size_t)(dt * 32 + r) * CELL + c0 + c4 * 4);
            swq[r * 33 + c4 * 4 + 0] = q.x; swq[r * 33 + c4 * 4 + 1] = q.y;
            swq[r * 33 + c4 * 4 + 2] = q.z; swq[r * 33 + c4 * 4 + 3] = q.w;
            swk[r * 33 + c4 * 4 + 0] = k.x; swk[r * 33 + c4 * 4 + 1] = k.y;
            swk[r * 33 + c4 * 4 + 2] = k.z; swk[r * 33 + c4 * 4 + 3] = k.w;
        }
        BARB();

        float accq[4][4] = {}, acck[4][4] = {};
        for (int cc = 0; cc < 32; cc++) {
            float aq[4], ak[4], bv[4];
#pragma unroll
            for (int i = 0; i < 4; i++) {
                aq[i] = swq[(ty * 4 + i) * 33 + cc];
                ak[i] = swk[(ty * 4 + i) * 33 + cc];
            }
#pragma unroll
            for (int j = 0; j < 4; j++) bv[j] = sbb[(tx * 4 + j) * 33 + cc];
#pragma unroll
            for (int i = 0; i < 4; i++)
#pragma unroll
                for (int j = 0; j < 4; j++) {
                    accq[i][j] += aq[i] * bv[j];
                    acck[i][j] += ak[i] * bv[j];
                }
        }
#pragma unroll
        for (int i = 0; i < 4; i++)
#pragma unroll
            for (int j = 0; j < 4; j++) {
                int d = dt * 32 + ty * 4 + i;
                int n = tx * 4 + j;
                g_bqp[(size_t)cb * (DD * NN) + d * 64 + n] = accq[i][j];
                g_bkp[(size_t)cb * (DD * NN) + d * 64 + n] = acck[i][j];
            }
        __threadfence();
        BARB();
        if (t2 == 0) atomicAdd(&g_f_bq, 1);
    } else {
        // PROJ for (dt of 16 d-rows, b): waits f_bq
        int id = bid - 512;                 // 0..511
        int dt = id >> 4, b = id & 15;      // dt 0..31
        int tx = t2 & 15, ty = t2 >> 4;     // ty 0..7
        float* sc     = poolB;              // 64 x 65 = 4160
        float* swqp   = poolB + 4160;       // 16 x 65 = 1040
        float* swkp   = poolB + 5200;       // 1040
        float* s_dbar = poolB + 6240;       // 16
        float* s_part = poolB + 6256;       // 128

        float ap = 1.f + alpha[0];
        float s3 = ap * ap * ap;
        float tb = ap * ap + ap + 1.f;

        if (t2 == 0) {
            while (atomicAdd(&g_f_bq, 0) < 512) __nanosleep(64);
        }
        BARB();
        __threadfence();

        // dbar[b,:]
        {
            int q = t2 & 15, g = t2 >> 4;   // g 0..7
            const float* dbase = dctx + (size_t)b * NN * QQ;
            float s = 0.f;
#pragma unroll
            for (int jj = 0; jj < 8; jj++) s += dbase[(g * 8 + jj) * QQ + q];
            s_part[t2] = s;
            BARB();
            if (t2 < 16) {
                float acc = 0.f;
#pragma unroll
                for (int gg = 0; gg < 8; gg++) acc += s_part[gg * 16 + t2];
                s_dbar[t2] = acc * (1.f / 64.f);
            }
        }

        // c tile: 64x64 = 1024 float4 / 128 thr = 8 iters
#pragma unroll
        for (int it = 0; it < 8; it++) {
            int idx = t2 + 128 * it;
            int rr = idx >> 4, cv = idx & 15;
            float4 v = *(const float4*)(c + (size_t)(b * NN + rr) * PP + cv * 4);
            sc[rr * 65 + cv * 4 + 0] = v.x; sc[rr * 65 + cv * 4 + 1] = v.y;
            sc[rr * 65 + cv * 4 + 2] = v.z; sc[rr * 65 + cv * 4 + 3] = v.w;
        }
        BARB();

        // wqd/wkd tile: 16 rows x 64 p = 1024 tasks / 128 = 8 iters
#pragma unroll
        for (int it = 0; it < 8; it++) {
            int idx = t2 + 128 * it;
            int rr = idx >> 6, p = idx & 63;
            const float* wqr = wq + (size_t)(dt * 16 + rr) * CELL + p * 16;
            const float* wkr = wk + (size_t)(dt * 16 + rr) * CELL + p * 16;
            float sq = 0.f, sk = 0.f;
#pragma unroll
            for (int q = 0; q < 16; q++) {
                float dv = s_dbar[q];
                sq += dv * wqr[q];
                sk += dv * wkr[q];
            }
            swqp[rr * 65 + p] = sq;
            swkp[rr * 65 + p] = sk;
        }
        BARB();

        float accq[2][4] = {}, acck[2][4] = {};
        for (int p = 0; p < PP; p++) {
            float aq[2], ak[2], bv[4];
#pragma unroll
            for (int i = 0; i < 2; i++) {
                aq[i] = swqp[(ty * 2 + i) * 65 + p];
                ak[i] = swkp[(ty * 2 + i) * 65 + p];
            }
#pragma unroll
            for (int j = 0; j < 4; j++) bv[j] = sc[(tx * 4 + j) * 65 + p];
#pragma unroll
            for (int i = 0; i < 2; i++)
#pragma unroll
                for (int j = 0; j < 4; j++) {
                    accq[i][j] += aq[i] * bv[j];
                    acck[i][j] += ak[i] * bv[j];
                }
        }
#pragma unroll
        for (int i = 0; i < 2; i++) {
            int d = dt * 16 + ty * 2 + i;
            float4 bq4 = {0.f, 0.f, 0.f, 0.f};
            float4 bk4 = {0.f, 0.f, 0.f, 0.f};
#pragma unroll
            for (int cb = 0; cb < 32; cb++) {
                float4 vq = *(const float4*)(g_bqp + (size_t)cb * (DD * NN) + d * 64 + tx * 4);
                float4 vk = *(const float4*)(g_bkp + (size_t)cb * (DD * NN) + d * 64 + tx * 4);
                bq4.x += vq.x; bq4.y += vq.y; bq4.z += vq.z; bq4.w += vq.w;
                bk4.x += vk.x; bk4.y += vk.y; bk4.z += vk.z; bk4.w += vk.w;
            }
            float bqa[4] = {bq4.x, bq4.y, bq4.z, bq4.w};
            float bka[4] = {bk4.x, bk4.y, bk4.z, bk4.w};
#pragma unroll
            for (int j = 0; j < 4; j++) {
                int n = tx * 4 + j;
                long long o = (long long)b * (DD * NN) + d * NN + n;
                out[OFF_Q + o] = s3 * accq[i][j] + tb * bqa[j];
                out[OFF_K + o] = s3 * acck[i][j] + tb * bka[j];
            }
        }
        BARB();
    }

    // ---- Done counting + flag reset for next graph replay ----
    if (t2 == 0) {
        int dn = atomicAdd(&g_done, 1);
        if (dn == 1023) {
            g_f_abn = 0; g_f_biasbar = 0; g_f_bq = 0; g_done = 0;
            __threadfence();
        }
    }
}

// ---------------------------------------------------------------------------
extern "C" void kernel_launch(void* const* d_in, const int* in_sizes, int n_in,
                              void* d_out, int out_size) {
    const float* a      = (const float*)d_in[0];
    const float* b      = (const float*)d_in[1];
    const float* c      = (const float*)d_in[2];
    const float* dctx   = (const float*)d_in[3];
    const float* alpha  = (const float*)d_in[4];
    const float* bias   = (const float*)d_in[5];
    const float* wq     = (const float*)d_in[6];
    const float* wk     = (const float*)d_in[7];
    const float* abd_w  = (const float*)d_in[8];
    const float* abd_b  = (const float*)d_in[9];
    const float* ctx_w  = (const float*)d_in[10];
    const float* ctx_b  = (const float*)d_in[11];
    const float* w1     = (const float*)d_in[12];
    const float* b1     = (const float*)d_in[13];
    const float* w_prob = (const float*)d_in[14];
    const float* b_prob = (const float*)d_in[15];
    float* out = (float*)d_out;

    k_fused<<<1024, 384>>>(a, b, c, dctx, alpha, bias, wq, wk,
                           abd_w, abd_b, ctx_w, ctx_b, w1, b1, w_prob, b_prob, out);
}